// round 2
// baseline (speedup 1.0000x reference)
#include <cuda_runtime.h>
#include <cuda_bf16.h>
#include <math.h>

#define B_ 4
#define H_ 8
#define N_ 1024
#define C_ 64
#define INV_SCALE (1.0f/32.0f)

// ---- device scratch (no allocation allowed) ----
__device__ float g_A[H_][C_][C_];       // Wq^T Wk per head
__device__ float g_Bq[H_][C_][3];       // Wq^T Wlq
__device__ float g_bq[H_][C_];          // Wq^T blq
__device__ float g_G[B_][H_][C_][N_];   // reduced K' operand (8 MB)
__device__ float g_WvT[68][H_ * N_];    // rows 0..63 Wv^T, 64..66 Wlv^T, 67 blv

// ============================================================
// Kernel 1: per-head A, Bq, bq.  grid (H,4), 256 thr
// ============================================================
__global__ void k_prep(const float* __restrict__ Wq, const float* __restrict__ Wk,
                       const float* __restrict__ Wlq, const float* __restrict__ blq) {
    __shared__ float wq_s[64][64];
    __shared__ float wk_s[64][64];
    const int h = blockIdx.x;
    const int t = threadIdx.x;
    const int cp = blockIdx.y * 16 + (t & 15);
    const int c0 = t >> 4;                      // 0..15
    float acc0 = 0.f, acc1 = 0.f, acc2 = 0.f, acc3 = 0.f;
    float b0 = 0.f, b1 = 0.f, b2 = 0.f, bb = 0.f;

    for (int ch = 0; ch < 16; ch++) {
        __syncthreads();
        const int rb = h * N_ + ch * 64;
        for (int i = t; i < 64 * 16; i += 256) {
            int r = i >> 4, q = i & 15;
            ((float4*)wq_s[r])[q] = ((const float4*)(Wq + (size_t)(rb + r) * 64))[q];
            ((float4*)wk_s[r])[q] = ((const float4*)(Wk + (size_t)(rb + r) * 64))[q];
        }
        __syncthreads();
        #pragma unroll 8
        for (int d = 0; d < 64; d++) {
            float kv = wk_s[d][cp];
            acc0 += wq_s[d][c0     ] * kv;
            acc1 += wq_s[d][c0 + 16] * kv;
            acc2 += wq_s[d][c0 + 32] * kv;
            acc3 += wq_s[d][c0 + 48] * kv;
        }
        if (blockIdx.y == 0 && t < 64) {
            #pragma unroll 8
            for (int d = 0; d < 64; d++) {
                float wv = wq_s[d][t];
                size_t gd = (size_t)(rb + d);
                b0 += wv * Wlq[gd * 3 + 0];
                b1 += wv * Wlq[gd * 3 + 1];
                b2 += wv * Wlq[gd * 3 + 2];
                bb += wv * blq[gd];
            }
        }
    }
    g_A[h][c0     ][cp] = acc0;
    g_A[h][c0 + 16][cp] = acc1;
    g_A[h][c0 + 32][cp] = acc2;
    g_A[h][c0 + 48][cp] = acc3;
    if (blockIdx.y == 0 && t < 64) {
        g_Bq[h][t][0] = b0; g_Bq[h][t][1] = b1; g_Bq[h][t][2] = b2;
        g_bq[h][t] = bb;
    }
}

// ============================================================
// Kernel 1b: build extended transposed V weights. grid 256, 256 thr
// ============================================================
__global__ void k_wvT(const float* __restrict__ Wv, const float* __restrict__ Wlv,
                      const float* __restrict__ blv) {
    __shared__ float tile[32][65];
    const int r0 = blockIdx.x * 32;
    const int t = threadIdx.x;
    for (int i = t; i < 32 * 64; i += 256) {
        int r = i >> 6, c = i & 63;
        tile[r][c] = Wv[(size_t)(r0 + r) * 64 + c];
    }
    __syncthreads();
    for (int i = t; i < 64 * 32; i += 256) {
        int c = i >> 5, r = i & 31;
        g_WvT[c][r0 + r] = tile[r][c];
    }
    if (t < 32) {
        size_t gr = (size_t)(r0 + t);
        g_WvT[64][r0 + t] = Wlv[gr * 3 + 0];
        g_WvT[65][r0 + t] = Wlv[gr * 3 + 1];
        g_WvT[66][r0 + t] = Wlv[gr * 3 + 2];
        g_WvT[67][r0 + t] = blv[gr];
    }
}

// ============================================================
// Kernel 2: G[b,h,c,m] = A·ns + Bq·coord + bq.  grid (B*H, 8), 256 thr
// dyn smem: At[64][68] + ns[64][128] + cs[3][128] + Bq[64][4] + bq[64]
// ============================================================
__global__ void k_buildG(const float* __restrict__ neighbors,
                         const float* __restrict__ coord) {
    extern __shared__ float sm[];
    float* At   = sm;                 // [64][68]
    float* ns_s = At + 64 * 68;       // [64][128]
    float* cs   = ns_s + 64 * 128;    // [3][128]
    float* Bq_s = cs + 3 * 128;       // [64][4]
    float* bq_s = Bq_s + 64 * 4;      // [64]

    const int b = blockIdx.x >> 3, h = blockIdx.x & 7;
    const int m0 = blockIdx.y * 128;
    const int t = threadIdx.x;

    for (int i = t; i < 64 * 64; i += 256) {
        int c = i >> 6, cp = i & 63;
        At[cp * 68 + c] = g_A[h][c][cp];
    }
    for (int i = t; i < 64 * 32; i += 256) {
        int cp = i >> 5, q = i & 31;
        ((float4*)(ns_s + cp * 128))[q] =
            ((const float4*)(neighbors + ((size_t)b * C_ + cp) * N_ + m0))[q];
    }
    for (int i = t; i < 3 * 32; i += 256) {
        int j = i >> 5, q = i & 31;
        ((float4*)(cs + j * 128))[q] =
            ((const float4*)(coord + ((size_t)b * 3 + j) * N_ + m0))[q];
    }
    for (int i = t; i < 64; i += 256) {
        Bq_s[i * 4 + 0] = g_Bq[h][i][0];
        Bq_s[i * 4 + 1] = g_Bq[h][i][1];
        Bq_s[i * 4 + 2] = g_Bq[h][i][2];
        bq_s[i] = g_bq[h][i];
    }
    __syncthreads();

    const int tc = t >> 5;        // c0 = tc*8
    const int tm = t & 31;        // m = tm*4
    const int c0 = tc * 8;

    float acc[8][4];
    #pragma unroll
    for (int i = 0; i < 8; i++) {
        const int c = c0 + i;
        const float bz = bq_s[c];
        const float q0 = Bq_s[c * 4], q1 = Bq_s[c * 4 + 1], q2 = Bq_s[c * 4 + 2];
        #pragma unroll
        for (int k = 0; k < 4; k++) {
            const int m = tm * 4 + k;
            acc[i][k] = bz + q0 * cs[m] + q1 * cs[128 + m] + q2 * cs[256 + m];
        }
    }
    #pragma unroll 4
    for (int cp = 0; cp < 64; cp++) {
        float4 nv = ((float4*)(ns_s + cp * 128))[tm];
        float4 a0 = *(float4*)(At + cp * 68 + c0);
        float4 a1 = *(float4*)(At + cp * 68 + c0 + 4);
        acc[0][0] += a0.x*nv.x; acc[0][1] += a0.x*nv.y; acc[0][2] += a0.x*nv.z; acc[0][3] += a0.x*nv.w;
        acc[1][0] += a0.y*nv.x; acc[1][1] += a0.y*nv.y; acc[1][2] += a0.y*nv.z; acc[1][3] += a0.y*nv.w;
        acc[2][0] += a0.z*nv.x; acc[2][1] += a0.z*nv.y; acc[2][2] += a0.z*nv.z; acc[2][3] += a0.z*nv.w;
        acc[3][0] += a0.w*nv.x; acc[3][1] += a0.w*nv.y; acc[3][2] += a0.w*nv.z; acc[3][3] += a0.w*nv.w;
        acc[4][0] += a1.x*nv.x; acc[4][1] += a1.x*nv.y; acc[4][2] += a1.x*nv.z; acc[4][3] += a1.x*nv.w;
        acc[5][0] += a1.y*nv.x; acc[5][1] += a1.y*nv.y; acc[5][2] += a1.y*nv.z; acc[5][3] += a1.y*nv.w;
        acc[6][0] += a1.z*nv.x; acc[6][1] += a1.z*nv.y; acc[6][2] += a1.z*nv.z; acc[6][3] += a1.z*nv.w;
        acc[7][0] += a1.w*nv.x; acc[7][1] += a1.w*nv.y; acc[7][2] += a1.w*nv.z; acc[7][3] += a1.w*nv.w;
    }
    #pragma unroll
    for (int i = 0; i < 8; i++)
        *((float4*)(&g_G[b][h][c0 + i][m0]) + tm) =
            make_float4(acc[i][0], acc[i][1], acc[i][2], acc[i][3]);
}

// ============================================================
// Kernel 3: energy -> softmax -> elementwise V' epilogue
// grid (B*H, N/32), 256 thr, ~184 KB dyn smem
// ============================================================
struct SM3 {
    float E[32][1028];
    float xs[64][32];
    float nse[68][32];
    float gw[68][132];
};

__global__ void __launch_bounds__(256, 1) k_main(
    const float* __restrict__ x, const float* __restrict__ neighbors,
    const float* __restrict__ coord, float* __restrict__ out) {
    extern __shared__ char smraw[];
    SM3& s = *reinterpret_cast<SM3*>(smraw);

    const int b = blockIdx.x >> 3, h = blockIdx.x & 7;
    const int n0 = blockIdx.y * 32;
    const int t = threadIdx.x;

    for (int i = t; i < 64 * 8; i += 256) {
        int c = i >> 3, q = i & 7;
        ((float4*)s.xs[c])[q]  = ((const float4*)(x + ((size_t)b * C_ + c) * N_ + n0))[q];
        ((float4*)s.nse[c])[q] = ((const float4*)(neighbors + ((size_t)b * C_ + c) * N_ + n0))[q];
    }
    if (t < 24) {
        int j = t >> 3, q = t & 7;
        ((float4*)s.nse[64 + j])[q] = ((const float4*)(coord + ((size_t)b * 3 + j) * N_ + n0))[q];
    } else if (t < 32) {
        ((float4*)s.nse[67])[t - 24] = make_float4(1.f, 1.f, 1.f, 1.f);
    }

    // ---- pass 1: energy ----
    const int tn = t >> 5, tm = t & 31;
    for (int mc = 0; mc < 8; mc++) {
        __syncthreads();
        for (int i = t; i < 64 * 32; i += 256) {
            int c = i >> 5, q = i & 31;
            ((float4*)s.gw[c])[q] = ((const float4*)(&g_G[b][h][c][mc * 128]))[q];
        }
        __syncthreads();
        float acc[4][4] = {};
        #pragma unroll 8
        for (int c = 0; c < 64; c++) {
            float4 xv = *(const float4*)&s.xs[c][tn * 4];
            float4 gv = *(const float4*)&s.gw[c][tm * 4];
            acc[0][0] += xv.x*gv.x; acc[0][1] += xv.x*gv.y; acc[0][2] += xv.x*gv.z; acc[0][3] += xv.x*gv.w;
            acc[1][0] += xv.y*gv.x; acc[1][1] += xv.y*gv.y; acc[1][2] += xv.y*gv.z; acc[1][3] += xv.y*gv.w;
            acc[2][0] += xv.z*gv.x; acc[2][1] += xv.z*gv.y; acc[2][2] += xv.z*gv.z; acc[2][3] += xv.z*gv.w;
            acc[3][0] += xv.w*gv.x; acc[3][1] += xv.w*gv.y; acc[3][2] += xv.w*gv.z; acc[3][3] += xv.w*gv.w;
        }
        const int mb = mc * 128 + tm * 4;
        #pragma unroll
        for (int i = 0; i < 4; i++)
            *(float4*)&s.E[tn * 4 + i][mb] =
                make_float4(acc[i][0], acc[i][1], acc[i][2], acc[i][3]);
    }
    __syncthreads();

    // ---- softmax rows ----
    {
        const int w = t >> 5, lane = t & 31;
        #pragma unroll
        for (int rr = 0; rr < 4; rr++) {
            const int r = w * 4 + rr;
            float pv[32];
            float mx = -1e30f;
            #pragma unroll
            for (int j = 0; j < 32; j++) { pv[j] = s.E[r][lane + 32 * j]; mx = fmaxf(mx, pv[j]); }
            #pragma unroll
            for (int o = 16; o; o >>= 1) mx = fmaxf(mx, __shfl_xor_sync(0xffffffffu, mx, o));
            float ss = 0.f;
            #pragma unroll
            for (int j = 0; j < 32; j++) { pv[j] = __expf((pv[j] - mx) * INV_SCALE); ss += pv[j]; }
            #pragma unroll
            for (int o = 16; o; o >>= 1) ss += __shfl_xor_sync(0xffffffffu, ss, o);
            const float rinv = 1.0f / ss;
            #pragma unroll
            for (int j = 0; j < 32; j++) s.E[r][lane + 32 * j] = pv[j] * rinv;
        }
    }

    // ---- pass 2: V' + elementwise combine + store ----
    const int td = t >> 3, tn2 = t & 7;
    for (int dc = 0; dc < 8; dc++) {
        __syncthreads();
        for (int i = t; i < 68 * 32; i += 256) {
            int cc = i >> 5, q = i & 31;
            ((float4*)s.gw[cc])[q] =
                ((const float4*)(g_WvT[cc] + h * N_ + dc * 128))[q];
        }
        __syncthreads();
        float acc[4][4] = {};      // [k=d][i=n]
        #pragma unroll 4
        for (int cc = 0; cc < 68; cc++) {
            float4 xv = *(const float4*)&s.nse[cc][tn2 * 4];
            float4 gv = *(const float4*)&s.gw[cc][td * 4];
            acc[0][0] += gv.x*xv.x; acc[0][1] += gv.x*xv.y; acc[0][2] += gv.x*xv.z; acc[0][3] += gv.x*xv.w;
            acc[1][0] += gv.y*xv.x; acc[1][1] += gv.y*xv.y; acc[1][2] += gv.y*xv.z; acc[1][3] += gv.y*xv.w;
            acc[2][0] += gv.z*xv.x; acc[2][1] += gv.z*xv.y; acc[2][2] += gv.z*xv.z; acc[2][3] += gv.z*xv.w;
            acc[3][0] += gv.w*xv.x; acc[3][1] += gv.w*xv.y; acc[3][2] += gv.w*xv.z; acc[3][3] += gv.w*xv.w;
        }
        float Ea[4][4];
        #pragma unroll
        for (int i = 0; i < 4; i++) {
            float4 Ev = *(const float4*)&s.E[tn2 * 4 + i][dc * 128 + td * 4];
            Ea[i][0] = Ev.x; Ea[i][1] = Ev.y; Ea[i][2] = Ev.z; Ea[i][3] = Ev.w;
        }
        #pragma unroll
        for (int k = 0; k < 4; k++) {
            size_t row = (size_t)b * 8192 + (size_t)h * N_ + dc * 128 + td * 4 + k;
            float4 o = make_float4(acc[k][0] * Ea[0][k], acc[k][1] * Ea[1][k],
                                   acc[k][2] * Ea[2][k], acc[k][3] * Ea[3][k]);
            *(float4*)(out + row * N_ + n0 + tn2 * 4) = o;
        }
    }
}

// ============================================================
extern "C" void kernel_launch(void* const* d_in, const int* in_sizes, int n_in,
                              void* d_out, int out_size) {
    const float* coordinate = (const float*)d_in[0];
    const float* x          = (const float*)d_in[1];
    const float* neighbors  = (const float*)d_in[2];
    const float* Wq         = (const float*)d_in[3];
    const float* Wk         = (const float*)d_in[4];
    const float* Wv         = (const float*)d_in[5];
    const float* Wlq        = (const float*)d_in[6];
    const float* blq        = (const float*)d_in[7];
    const float* Wlv        = (const float*)d_in[8];
    const float* blv        = (const float*)d_in[9];
    float* out = (float*)d_out;

    static bool attr_set = false;
    if (!attr_set) {
        cudaFuncSetAttribute(k_buildG, cudaFuncAttributeMaxDynamicSharedMemorySize, 56 * 1024);
        cudaFuncSetAttribute(k_main, cudaFuncAttributeMaxDynamicSharedMemorySize, 192 * 1024);
        attr_set = true;
    }

    k_prep<<<dim3(H_, 4), 256>>>(Wq, Wk, Wlq, blq);
    k_wvT<<<256, 256>>>(Wv, Wlv, blv);
    k_buildG<<<dim3(B_ * H_, 8), 256, 53248>>>(neighbors, coordinate);
    k_main<<<dim3(B_ * H_, 32), 256, sizeof(SM3)>>>(x, neighbors, coordinate, out);
}

// round 3
// speedup vs baseline: 1.6515x; 1.6515x over previous
#include <cuda_runtime.h>
#include <cuda_bf16.h>
#include <math.h>

#define B_ 4
#define H_ 8
#define N_ 1024
#define C_ 64
#define INV_SCALE (1.0f/32.0f)

// ---- device scratch ----
__device__ float g_Apart[16][H_][C_][C_];   // partial Wq^T Wk (per 64-d chunk)
__device__ float g_bpart[16][H_][C_][4];    // partial [Bq0,Bq1,Bq2,bq]
__device__ float g_A[H_][C_][C_];
__device__ float g_Bq4[H_][C_][4];          // Bq(3) + bq packed
__device__ float g_G[B_][H_][C_][N_];       // 8 MB reduced operand
__device__ float g_WvT[68][H_ * N_];        // Wv^T ++ Wlv^T ++ blv

// ---- packed f32x2 helpers ----
__device__ __forceinline__ unsigned long long pk2(float f) {
    unsigned long long u; unsigned int r = __float_as_uint(f);
    asm("mov.b64 %0, {%1, %1};" : "=l"(u) : "r"(r));
    return u;
}
__device__ __forceinline__ void fma2(unsigned long long& d, unsigned long long a, unsigned long long b) {
    asm("fma.rn.f32x2 %0, %1, %2, %0;" : "+l"(d) : "l"(a), "l"(b));
}
__device__ __forceinline__ void mul2(unsigned long long& d, unsigned long long a, unsigned long long b) {
    asm("mul.rn.f32x2 %0, %1, %2;" : "=l"(d) : "l"(a), "l"(b));
}
__device__ __forceinline__ void upk(unsigned long long u, float& lo, float& hi) {
    unsigned int a, b;
    asm("mov.b64 {%0,%1}, %2;" : "=r"(a), "=r"(b) : "l"(u));
    lo = __uint_as_float(a); hi = __uint_as_float(b);
}

// ============================================================
// k_prep1: partial A/Bq/bq per 64-d chunk. grid (H,16), 256 thr
// ============================================================
__global__ void k_prep1(const float* __restrict__ Wq, const float* __restrict__ Wk,
                        const float* __restrict__ Wlq, const float* __restrict__ blq) {
    __shared__ float wq_s[64][68];
    __shared__ float wk_s[64][68];
    __shared__ float wl_s[64][4];
    const int h = blockIdx.x, dz = blockIdx.y;
    const int t = threadIdx.x;
    const int rb = h * N_ + dz * 64;

    for (int i = t; i < 64 * 16; i += 256) {
        int r = i >> 4, q = i & 15;
        ((float4*)wq_s[r])[q] = ((const float4*)(Wq + (size_t)(rb + r) * 64))[q];
        ((float4*)wk_s[r])[q] = ((const float4*)(Wk + (size_t)(rb + r) * 64))[q];
    }
    if (t < 64) {
        wl_s[t][0] = Wlq[(size_t)(rb + t) * 3 + 0];
        wl_s[t][1] = Wlq[(size_t)(rb + t) * 3 + 1];
        wl_s[t][2] = Wlq[(size_t)(rb + t) * 3 + 2];
        wl_s[t][3] = blq[rb + t];
    }
    __syncthreads();

    const int rg = t >> 4, cg = t & 15;
    const int c0 = rg * 4, cp0 = cg * 4;
    float acc[4][4] = {};
    #pragma unroll 8
    for (int d = 0; d < 64; d++) {
        float4 qv = *(float4*)&wq_s[d][c0];
        float4 kv = *(float4*)&wk_s[d][cp0];
        acc[0][0]+=qv.x*kv.x; acc[0][1]+=qv.x*kv.y; acc[0][2]+=qv.x*kv.z; acc[0][3]+=qv.x*kv.w;
        acc[1][0]+=qv.y*kv.x; acc[1][1]+=qv.y*kv.y; acc[1][2]+=qv.y*kv.z; acc[1][3]+=qv.y*kv.w;
        acc[2][0]+=qv.z*kv.x; acc[2][1]+=qv.z*kv.y; acc[2][2]+=qv.z*kv.z; acc[2][3]+=qv.z*kv.w;
        acc[3][0]+=qv.w*kv.x; acc[3][1]+=qv.w*kv.y; acc[3][2]+=qv.w*kv.z; acc[3][3]+=qv.w*kv.w;
    }
    #pragma unroll
    for (int i = 0; i < 4; i++)
        *(float4*)&g_Apart[dz][h][c0 + i][cp0] =
            make_float4(acc[i][0], acc[i][1], acc[i][2], acc[i][3]);

    if (t < 64) {
        float s0 = 0.f, s1 = 0.f, s2 = 0.f, s3 = 0.f;
        #pragma unroll 8
        for (int d = 0; d < 64; d++) {
            float wv = wq_s[d][t];
            float4 wl = *(float4*)wl_s[d];
            s0 += wv * wl.x; s1 += wv * wl.y; s2 += wv * wl.z; s3 += wv * wl.w;
        }
        *(float4*)g_bpart[dz][h][t] = make_float4(s0, s1, s2, s3);
    }
}

// ============================================================
// k_prep2: reduce 16 partials. grid (H,16), 256 thr
// ============================================================
__global__ void k_prep2() {
    const int h = blockIdx.x;
    const int e = blockIdx.y * 256 + threadIdx.x;   // 0..4095
    const int c = e >> 6, cp = e & 63;
    float s = 0.f;
    #pragma unroll
    for (int dz = 0; dz < 16; dz++) s += g_Apart[dz][h][c][cp];
    g_A[h][c][cp] = s;
    if (blockIdx.y == 0 && threadIdx.x < 64) {
        const int cc = threadIdx.x;
        float4 acc = make_float4(0.f, 0.f, 0.f, 0.f);
        #pragma unroll
        for (int dz = 0; dz < 16; dz++) {
            float4 v = *(float4*)g_bpart[dz][h][cc];
            acc.x += v.x; acc.y += v.y; acc.z += v.z; acc.w += v.w;
        }
        *(float4*)g_Bq4[h][cc] = acc;
    }
}

// ============================================================
// k_wvT: extended transposed V weights. grid 256, 256 thr
// ============================================================
__global__ void k_wvT(const float* __restrict__ Wv, const float* __restrict__ Wlv,
                      const float* __restrict__ blv) {
    __shared__ float tile[32][65];
    const int r0 = blockIdx.x * 32;
    const int t = threadIdx.x;
    for (int i = t; i < 32 * 64; i += 256) {
        int r = i >> 6, c = i & 63;
        tile[r][c] = Wv[(size_t)(r0 + r) * 64 + c];
    }
    __syncthreads();
    for (int i = t; i < 64 * 32; i += 256) {
        int c = i >> 5, r = i & 31;
        g_WvT[c][r0 + r] = tile[r][c];
    }
    if (t < 32) {
        size_t gr = (size_t)(r0 + t);
        g_WvT[64][r0 + t] = Wlv[gr * 3 + 0];
        g_WvT[65][r0 + t] = Wlv[gr * 3 + 1];
        g_WvT[66][r0 + t] = Wlv[gr * 3 + 2];
        g_WvT[67][r0 + t] = blv[gr];
    }
}

// ============================================================
// k_buildG: G = A·ns + Bq·coord + bq. grid (B*H, 8), 256 thr
// ============================================================
__global__ void k_buildG(const float* __restrict__ neighbors,
                         const float* __restrict__ coord) {
    extern __shared__ float sm[];
    float* At   = sm;                 // [64][68]
    float* ns_s = At + 64 * 68;       // [64][128]
    float* cs   = ns_s + 64 * 128;    // [3][128]
    float* Bq_s = cs + 3 * 128;       // [64][4]

    const int b = blockIdx.x >> 3, h = blockIdx.x & 7;
    const int m0 = blockIdx.y * 128;
    const int t = threadIdx.x;

    for (int i = t; i < 64 * 64; i += 256) {
        int c = i >> 6, cp = i & 63;
        At[cp * 68 + c] = g_A[h][c][cp];
    }
    for (int i = t; i < 64 * 32; i += 256) {
        int cp = i >> 5, q = i & 31;
        ((float4*)(ns_s + cp * 128))[q] =
            ((const float4*)(neighbors + ((size_t)b * C_ + cp) * N_ + m0))[q];
    }
    for (int i = t; i < 3 * 32; i += 256) {
        int j = i >> 5, q = i & 31;
        ((float4*)(cs + j * 128))[q] =
            ((const float4*)(coord + ((size_t)b * 3 + j) * N_ + m0))[q];
    }
    for (int i = t; i < 64; i += 256)
        *(float4*)(Bq_s + i * 4) = *(float4*)g_Bq4[h][i];
    __syncthreads();

    const int tc = t >> 5;
    const int tm = t & 31;
    const int c0 = tc * 8;

    float acc[8][4];
    #pragma unroll
    for (int i = 0; i < 8; i++) {
        const int c = c0 + i;
        const float q0 = Bq_s[c * 4], q1 = Bq_s[c * 4 + 1], q2 = Bq_s[c * 4 + 2], bz = Bq_s[c * 4 + 3];
        #pragma unroll
        for (int k = 0; k < 4; k++) {
            const int m = tm * 4 + k;
            acc[i][k] = bz + q0 * cs[m] + q1 * cs[128 + m] + q2 * cs[256 + m];
        }
    }
    #pragma unroll 4
    for (int cp = 0; cp < 64; cp++) {
        float4 nv = ((float4*)(ns_s + cp * 128))[tm];
        float4 a0 = *(float4*)(At + cp * 68 + c0);
        float4 a1 = *(float4*)(At + cp * 68 + c0 + 4);
        acc[0][0]+=a0.x*nv.x; acc[0][1]+=a0.x*nv.y; acc[0][2]+=a0.x*nv.z; acc[0][3]+=a0.x*nv.w;
        acc[1][0]+=a0.y*nv.x; acc[1][1]+=a0.y*nv.y; acc[1][2]+=a0.y*nv.z; acc[1][3]+=a0.y*nv.w;
        acc[2][0]+=a0.z*nv.x; acc[2][1]+=a0.z*nv.y; acc[2][2]+=a0.z*nv.z; acc[2][3]+=a0.z*nv.w;
        acc[3][0]+=a0.w*nv.x; acc[3][1]+=a0.w*nv.y; acc[3][2]+=a0.w*nv.z; acc[3][3]+=a0.w*nv.w;
        acc[4][0]+=a1.x*nv.x; acc[4][1]+=a1.x*nv.y; acc[4][2]+=a1.x*nv.z; acc[4][3]+=a1.x*nv.w;
        acc[5][0]+=a1.y*nv.x; acc[5][1]+=a1.y*nv.y; acc[5][2]+=a1.y*nv.z; acc[5][3]+=a1.y*nv.w;
        acc[6][0]+=a1.z*nv.x; acc[6][1]+=a1.z*nv.y; acc[6][2]+=a1.z*nv.z; acc[6][3]+=a1.z*nv.w;
        acc[7][0]+=a1.w*nv.x; acc[7][1]+=a1.w*nv.y; acc[7][2]+=a1.w*nv.z; acc[7][3]+=a1.w*nv.w;
    }
    #pragma unroll
    for (int i = 0; i < 8; i++)
        *((float4*)(&g_G[b][h][c0 + i][m0]) + tm) =
            make_float4(acc[i][0], acc[i][1], acc[i][2], acc[i][3]);
}

// ============================================================
// k_main: energy -> softmax -> elementwise V' epilogue
// grid (B*H, N/32), 512 thr, ~214 KB smem, packed f32x2 math
// ============================================================
struct SM3 {
    float E[32][1028];     // 131584 B
    float xs[64][32];      //   8192 B
    float nse[68][32];     //   8704 B
    float gw[68][260];     //  70720 B
};

__global__ void __launch_bounds__(512, 1) k_main(
    const float* __restrict__ x, const float* __restrict__ neighbors,
    const float* __restrict__ coord, float* __restrict__ out) {
    extern __shared__ char smraw[];
    SM3& s = *reinterpret_cast<SM3*>(smraw);

    const int b = blockIdx.x >> 3, h = blockIdx.x & 7;
    const int n0 = blockIdx.y * 32;
    const int t = threadIdx.x;
    const int w = t >> 5, lane = t & 31;

    for (int i = t; i < 64 * 8; i += 512) {
        int c = i >> 3, q = i & 7;
        ((float4*)s.xs[c])[q]  = ((const float4*)(x + ((size_t)b * C_ + c) * N_ + n0))[q];
        ((float4*)s.nse[c])[q] = ((const float4*)(neighbors + ((size_t)b * C_ + c) * N_ + n0))[q];
    }
    if (t < 24) {
        int j = t >> 3, q = t & 7;
        ((float4*)s.nse[64 + j])[q] = ((const float4*)(coord + ((size_t)b * 3 + j) * N_ + n0))[q];
    } else if (t < 32) {
        ((float4*)s.nse[67])[t - 24] = make_float4(1.f, 1.f, 1.f, 1.f);
    }

    // ---- pass 1: E[32][1024] = xs^T (K=64) G, chunks of 256 cols ----
    {
        const int rg = t >> 6;          // 0..7  rows rg*4..+3
        const int cg = t & 63;          // cols cg*4..+3
        for (int mc = 0; mc < 4; mc++) {
            __syncthreads();
            for (int i = t; i < 64 * 64; i += 512) {
                int c = i >> 6, q = i & 63;
                ((float4*)(s.gw[0] + c * 260))[q] =
                    ((const float4*)(&g_G[b][h][c][mc * 256]))[q];
            }
            __syncthreads();
            unsigned long long a01[4] = {}, a23[4] = {};
            #pragma unroll 8
            for (int c = 0; c < 64; c++) {
                float4 xv = *(float4*)&s.xs[c][rg * 4];
                float4 gv = *(float4*)(s.gw[0] + c * 260 + cg * 4);
                unsigned long long g01 = ((unsigned long long*)&gv)[0];
                unsigned long long g23 = ((unsigned long long*)&gv)[1];
                unsigned long long x0 = pk2(xv.x), x1 = pk2(xv.y), x2 = pk2(xv.z), x3 = pk2(xv.w);
                fma2(a01[0], x0, g01); fma2(a23[0], x0, g23);
                fma2(a01[1], x1, g01); fma2(a23[1], x1, g23);
                fma2(a01[2], x2, g01); fma2(a23[2], x2, g23);
                fma2(a01[3], x3, g01); fma2(a23[3], x3, g23);
            }
            const int mb = mc * 256 + cg * 4;
            #pragma unroll
            for (int i = 0; i < 4; i++) {
                float4 o;
                ((unsigned long long*)&o)[0] = a01[i];
                ((unsigned long long*)&o)[1] = a23[i];
                *(float4*)&s.E[rg * 4 + i][mb] = o;
            }
        }
    }
    __syncthreads();

    // ---- softmax: 16 warps x 2 rows ----
    #pragma unroll
    for (int rr = 0; rr < 2; rr++) {
        const int r = w * 2 + rr;
        float pv[32];
        float mx = -1e30f;
        #pragma unroll
        for (int j = 0; j < 32; j++) { pv[j] = s.E[r][lane + 32 * j]; mx = fmaxf(mx, pv[j]); }
        #pragma unroll
        for (int o = 16; o; o >>= 1) mx = fmaxf(mx, __shfl_xor_sync(0xffffffffu, mx, o));
        float ss = 0.f;
        #pragma unroll
        for (int j = 0; j < 32; j++) { pv[j] = __expf((pv[j] - mx) * INV_SCALE); ss += pv[j]; }
        #pragma unroll
        for (int o = 16; o; o >>= 1) ss += __shfl_xor_sync(0xffffffffu, ss, o);
        const float rinv = 1.0f / ss;
        #pragma unroll
        for (int j = 0; j < 32; j++) s.E[r][lane + 32 * j] = pv[j] * rinv;
    }

    // ---- pass 2: V'(K=68) * probs, chunks of 256 d-cols ----
    {
        const int dg = w * 4 + (lane >> 3);   // 0..63, d = dg*4
        const int ng = lane & 7;              // n = ng*4
        const size_t outbase = (size_t)b * 8192 + (size_t)h * N_;
        for (int dc = 0; dc < 4; dc++) {
            __syncthreads();
            for (int i = t; i < 68 * 64; i += 512) {
                int cc = i >> 6, q = i & 63;
                ((float4*)(s.gw[0] + cc * 260))[q] =
                    ((const float4*)(g_WvT[cc] + h * N_ + dc * 256))[q];
            }
            __syncthreads();
            // acc[i]: n-row i, packed d pairs (d01, d23)
            unsigned long long a01[4] = {}, a23[4] = {};
            #pragma unroll 4
            for (int cc = 0; cc < 68; cc++) {
                float4 xv = *(float4*)&s.nse[cc][ng * 4];
                float4 gv = *(float4*)(s.gw[0] + cc * 260 + dg * 4);
                unsigned long long g01 = ((unsigned long long*)&gv)[0];
                unsigned long long g23 = ((unsigned long long*)&gv)[1];
                unsigned long long x0 = pk2(xv.x), x1 = pk2(xv.y), x2 = pk2(xv.z), x3 = pk2(xv.w);
                fma2(a01[0], x0, g01); fma2(a23[0], x0, g23);
                fma2(a01[1], x1, g01); fma2(a23[1], x1, g23);
                fma2(a01[2], x2, g01); fma2(a23[2], x2, g23);
                fma2(a01[3], x3, g01); fma2(a23[3], x3, g23);
            }
            // multiply by probs and transpose-store
            float vc[4][4];
            #pragma unroll
            for (int i = 0; i < 4; i++) {
                float4 Ev = *(float4*)&s.E[ng * 4 + i][dc * 256 + dg * 4];
                unsigned long long e01 = ((unsigned long long*)&Ev)[0];
                unsigned long long e23 = ((unsigned long long*)&Ev)[1];
                mul2(a01[i], a01[i], e01);
                mul2(a23[i], a23[i], e23);
                upk(a01[i], vc[i][0], vc[i][1]);
                upk(a23[i], vc[i][2], vc[i][3]);
            }
            #pragma unroll
            for (int k = 0; k < 4; k++) {
                size_t row = outbase + dc * 256 + dg * 4 + k;
                *(float4*)(out + row * N_ + n0 + ng * 4) =
                    make_float4(vc[0][k], vc[1][k], vc[2][k], vc[3][k]);
            }
        }
    }
}

// ============================================================
extern "C" void kernel_launch(void* const* d_in, const int* in_sizes, int n_in,
                              void* d_out, int out_size) {
    const float* coordinate = (const float*)d_in[0];
    const float* x          = (const float*)d_in[1];
    const float* neighbors  = (const float*)d_in[2];
    const float* Wq         = (const float*)d_in[3];
    const float* Wk         = (const float*)d_in[4];
    const float* Wv         = (const float*)d_in[5];
    const float* Wlq        = (const float*)d_in[6];
    const float* blq        = (const float*)d_in[7];
    const float* Wlv        = (const float*)d_in[8];
    const float* blv        = (const float*)d_in[9];
    float* out = (float*)d_out;

    static bool attr_set = false;
    if (!attr_set) {
        cudaFuncSetAttribute(k_buildG, cudaFuncAttributeMaxDynamicSharedMemorySize, 56 * 1024);
        cudaFuncSetAttribute(k_main, cudaFuncAttributeMaxDynamicSharedMemorySize, 220 * 1024);
        attr_set = true;
    }

    k_prep1<<<dim3(H_, 16), 256>>>(Wq, Wk, Wlq, blq);
    k_prep2<<<dim3(H_, 16), 256>>>();
    k_wvT<<<256, 256>>>(Wv, Wlv, blv);
    k_buildG<<<dim3(B_ * H_, 8), 256, 53248>>>(neighbors, coordinate);
    k_main<<<dim3(B_ * H_, 32), 512, sizeof(SM3)>>>(x, neighbors, coordinate, out);
}

// round 4
// speedup vs baseline: 1.6631x; 1.0070x over previous
#include <cuda_runtime.h>
#include <cuda_bf16.h>
#include <math.h>

#define B_ 4
#define H_ 8
#define N_ 1024
#define C_ 64
#define INV_SCALE (1.0f/32.0f)

// ---- device scratch ----
__device__ float g_Apart[16][H_][C_][C_];
__device__ float g_bpart[16][H_][C_][4];
__device__ float g_A[H_][C_][C_];
__device__ float g_Bq4[H_][C_][4];
__device__ float g_G[B_][H_][C_][N_];       // 8 MB reduced operand
__device__ float g_WvT[68][H_ * N_];        // Wv^T ++ Wlv^T ++ blv

// ---- packed f32x2 helpers ----
__device__ __forceinline__ unsigned long long pk2(float f) {
    unsigned long long u; unsigned int r = __float_as_uint(f);
    asm("mov.b64 %0, {%1, %1};" : "=l"(u) : "r"(r));
    return u;
}
__device__ __forceinline__ void fma2(unsigned long long& d, unsigned long long a, unsigned long long b) {
    asm("fma.rn.f32x2 %0, %1, %2, %0;" : "+l"(d) : "l"(a), "l"(b));
}
__device__ __forceinline__ void mul2(unsigned long long& d, unsigned long long a, unsigned long long b) {
    asm("mul.rn.f32x2 %0, %1, %2;" : "=l"(d) : "l"(a), "l"(b));
}
__device__ __forceinline__ void upk(unsigned long long u, float& lo, float& hi) {
    unsigned int a, b;
    asm("mov.b64 {%0,%1}, %2;" : "=r"(a), "=r"(b) : "l"(u));
    lo = __uint_as_float(a); hi = __uint_as_float(b);
}

// ============================================================
// k_prep1: partial A/Bq/bq per 64-d chunk. grid (H,16), 256 thr
// ============================================================
__global__ void k_prep1(const float* __restrict__ Wq, const float* __restrict__ Wk,
                        const float* __restrict__ Wlq, const float* __restrict__ blq) {
    __shared__ float wq_s[64][68];
    __shared__ float wk_s[64][68];
    __shared__ float wl_s[64][4];
    const int h = blockIdx.x, dz = blockIdx.y;
    const int t = threadIdx.x;
    const int rb = h * N_ + dz * 64;

    for (int i = t; i < 64 * 16; i += 256) {
        int r = i >> 4, q = i & 15;
        ((float4*)wq_s[r])[q] = ((const float4*)(Wq + (size_t)(rb + r) * 64))[q];
        ((float4*)wk_s[r])[q] = ((const float4*)(Wk + (size_t)(rb + r) * 64))[q];
    }
    if (t < 64) {
        wl_s[t][0] = Wlq[(size_t)(rb + t) * 3 + 0];
        wl_s[t][1] = Wlq[(size_t)(rb + t) * 3 + 1];
        wl_s[t][2] = Wlq[(size_t)(rb + t) * 3 + 2];
        wl_s[t][3] = blq[rb + t];
    }
    __syncthreads();

    const int rg = t >> 4, cg = t & 15;
    const int c0 = rg * 4, cp0 = cg * 4;
    float acc[4][4] = {};
    #pragma unroll 8
    for (int d = 0; d < 64; d++) {
        float4 qv = *(float4*)&wq_s[d][c0];
        float4 kv = *(float4*)&wk_s[d][cp0];
        acc[0][0]+=qv.x*kv.x; acc[0][1]+=qv.x*kv.y; acc[0][2]+=qv.x*kv.z; acc[0][3]+=qv.x*kv.w;
        acc[1][0]+=qv.y*kv.x; acc[1][1]+=qv.y*kv.y; acc[1][2]+=qv.y*kv.z; acc[1][3]+=qv.y*kv.w;
        acc[2][0]+=qv.z*kv.x; acc[2][1]+=qv.z*kv.y; acc[2][2]+=qv.z*kv.z; acc[2][3]+=qv.z*kv.w;
        acc[3][0]+=qv.w*kv.x; acc[3][1]+=qv.w*kv.y; acc[3][2]+=qv.w*kv.z; acc[3][3]+=qv.w*kv.w;
    }
    #pragma unroll
    for (int i = 0; i < 4; i++)
        *(float4*)&g_Apart[dz][h][c0 + i][cp0] =
            make_float4(acc[i][0], acc[i][1], acc[i][2], acc[i][3]);

    if (t < 64) {
        float s0 = 0.f, s1 = 0.f, s2 = 0.f, s3 = 0.f;
        #pragma unroll 8
        for (int d = 0; d < 64; d++) {
            float wv = wq_s[d][t];
            float4 wl = *(float4*)wl_s[d];
            s0 += wv * wl.x; s1 += wv * wl.y; s2 += wv * wl.z; s3 += wv * wl.w;
        }
        *(float4*)g_bpart[dz][h][t] = make_float4(s0, s1, s2, s3);
    }
}

// ============================================================
// k_prep2: reduce 16 partials. grid (H,16), 256 thr
// ============================================================
__global__ void k_prep2() {
    const int h = blockIdx.x;
    const int e = blockIdx.y * 256 + threadIdx.x;
    const int c = e >> 6, cp = e & 63;
    float s = 0.f;
    #pragma unroll
    for (int dz = 0; dz < 16; dz++) s += g_Apart[dz][h][c][cp];
    g_A[h][c][cp] = s;
    if (blockIdx.y == 0 && threadIdx.x < 64) {
        const int cc = threadIdx.x;
        float4 acc = make_float4(0.f, 0.f, 0.f, 0.f);
        #pragma unroll
        for (int dz = 0; dz < 16; dz++) {
            float4 v = *(float4*)g_bpart[dz][h][cc];
            acc.x += v.x; acc.y += v.y; acc.z += v.z; acc.w += v.w;
        }
        *(float4*)g_Bq4[h][cc] = acc;
    }
}

// ============================================================
// k_wvT: extended transposed V weights. grid 256, 256 thr
// ============================================================
__global__ void k_wvT(const float* __restrict__ Wv, const float* __restrict__ Wlv,
                      const float* __restrict__ blv) {
    __shared__ float tile[32][65];
    const int r0 = blockIdx.x * 32;
    const int t = threadIdx.x;
    for (int i = t; i < 32 * 64; i += 256) {
        int r = i >> 6, c = i & 63;
        tile[r][c] = Wv[(size_t)(r0 + r) * 64 + c];
    }
    __syncthreads();
    for (int i = t; i < 64 * 32; i += 256) {
        int c = i >> 5, r = i & 31;
        g_WvT[c][r0 + r] = tile[r][c];
    }
    if (t < 32) {
        size_t gr = (size_t)(r0 + t);
        g_WvT[64][r0 + t] = Wlv[gr * 3 + 0];
        g_WvT[65][r0 + t] = Wlv[gr * 3 + 1];
        g_WvT[66][r0 + t] = Wlv[gr * 3 + 2];
        g_WvT[67][r0 + t] = blv[gr];
    }
}

// ============================================================
// k_buildG: G = A·ns + Bq·coord + bq. grid (B*H, 16), 256 thr
// m-chunks of 64 for grid occupancy (512 CTAs)
// ============================================================
__global__ void k_buildG(const float* __restrict__ neighbors,
                         const float* __restrict__ coord) {
    __shared__ float At[64 * 68];
    __shared__ float ns_s[64 * 64];
    __shared__ float cs[3 * 64];
    __shared__ float Bq_s[64 * 4];

    const int b = blockIdx.x >> 3, h = blockIdx.x & 7;
    const int m0 = blockIdx.y * 64;
    const int t = threadIdx.x;

    for (int i = t; i < 64 * 64; i += 256) {
        int c = i >> 6, cp = i & 63;
        At[cp * 68 + c] = g_A[h][c][cp];
    }
    for (int i = t; i < 64 * 16; i += 256) {
        int cp = i >> 4, q = i & 15;
        ((float4*)(ns_s + cp * 64))[q] =
            ((const float4*)(neighbors + ((size_t)b * C_ + cp) * N_ + m0))[q];
    }
    for (int i = t; i < 3 * 16; i += 256) {
        int j = i >> 4, q = i & 15;
        ((float4*)(cs + j * 64))[q] =
            ((const float4*)(coord + ((size_t)b * 3 + j) * N_ + m0))[q];
    }
    for (int i = t; i < 64; i += 256)
        *(float4*)(Bq_s + i * 4) = *(float4*)g_Bq4[h][i];
    __syncthreads();

    const int tc = t >> 5;        // 8 groups of 8 c-rows
    const int tm = t & 31;        // m pair index
    const int c0 = tc * 8;

    float acc[8][2];
    #pragma unroll
    for (int i = 0; i < 8; i++) {
        const int c = c0 + i;
        const float q0 = Bq_s[c * 4], q1 = Bq_s[c * 4 + 1], q2 = Bq_s[c * 4 + 2], bz = Bq_s[c * 4 + 3];
        #pragma unroll
        for (int k = 0; k < 2; k++) {
            const int m = tm * 2 + k;
            acc[i][k] = bz + q0 * cs[m] + q1 * cs[64 + m] + q2 * cs[128 + m];
        }
    }
    #pragma unroll 8
    for (int cp = 0; cp < 64; cp++) {
        float2 nv = ((float2*)(ns_s + cp * 64))[tm];
        float4 a0 = *(float4*)(At + cp * 68 + c0);
        float4 a1 = *(float4*)(At + cp * 68 + c0 + 4);
        acc[0][0]+=a0.x*nv.x; acc[0][1]+=a0.x*nv.y;
        acc[1][0]+=a0.y*nv.x; acc[1][1]+=a0.y*nv.y;
        acc[2][0]+=a0.z*nv.x; acc[2][1]+=a0.z*nv.y;
        acc[3][0]+=a0.w*nv.x; acc[3][1]+=a0.w*nv.y;
        acc[4][0]+=a1.x*nv.x; acc[4][1]+=a1.x*nv.y;
        acc[5][0]+=a1.y*nv.x; acc[5][1]+=a1.y*nv.y;
        acc[6][0]+=a1.z*nv.x; acc[6][1]+=a1.z*nv.y;
        acc[7][0]+=a1.w*nv.x; acc[7][1]+=a1.w*nv.y;
    }
    #pragma unroll
    for (int i = 0; i < 8; i++)
        *((float2*)(&g_G[b][h][c0 + i][m0]) + tm) = make_float2(acc[i][0], acc[i][1]);
}

// ============================================================
// k_main: energy -> softmax -> elementwise V' epilogue
// grid (B*H, N/32), 512 thr, ~214 KB smem, f32x2 + reg-prefetch pipeline
// ============================================================
struct SM3 {
    float E[32][1028];     // 131584 B
    float xs[64][32];      //   8192 B
    float nse[68][32];     //   8704 B
    float gw[68][260];     //  70720 B
};

__global__ void __launch_bounds__(512, 1) k_main(
    const float* __restrict__ x, const float* __restrict__ neighbors,
    const float* __restrict__ coord, float* __restrict__ out) {
    extern __shared__ char smraw[];
    SM3& s = *reinterpret_cast<SM3*>(smraw);

    const int b = blockIdx.x >> 3, h = blockIdx.x & 7;
    const int n0 = blockIdx.y * 32;
    const int t = threadIdx.x;
    const int w = t >> 5, lane = t & 31;

    for (int i = t; i < 64 * 8; i += 512) {
        int c = i >> 3, q = i & 7;
        ((float4*)s.xs[c])[q]  = ((const float4*)(x + ((size_t)b * C_ + c) * N_ + n0))[q];
        ((float4*)s.nse[c])[q] = ((const float4*)(neighbors + ((size_t)b * C_ + c) * N_ + n0))[q];
    }
    if (t < 24) {
        int j = t >> 3, q = t & 7;
        ((float4*)s.nse[64 + j])[q] = ((const float4*)(coord + ((size_t)b * 3 + j) * N_ + n0))[q];
    } else if (t < 32) {
        ((float4*)s.nse[67])[t - 24] = make_float4(1.f, 1.f, 1.f, 1.f);
    }
    // initial G chunk 0 load
    for (int i = t; i < 64 * 64; i += 512) {
        int c = i >> 6, q = i & 63;
        ((float4*)(s.gw[0] + c * 260))[q] = ((const float4*)(&g_G[b][h][c][0]))[q];
    }
    __syncthreads();

    // ---- pass 1: E[32][1024] = xs^T (K=64) G, chunks of 256, reg-prefetch ----
    {
        const int rg = t >> 6;          // rows rg*4..+3
        const int cg = t & 63;          // cols cg*4..+3
        for (int mc = 0; mc < 4; mc++) {
            float4 pf[8];
            if (mc < 3) {
                #pragma unroll
                for (int q = 0; q < 8; q++) {
                    int idx = q * 512 + t;
                    pf[q] = ((const float4*)(&g_G[b][h][idx >> 6][(mc + 1) * 256]))[idx & 63];
                }
            }
            unsigned long long a01[4] = {}, a23[4] = {};
            #pragma unroll 8
            for (int c = 0; c < 64; c++) {
                float4 xv = *(float4*)&s.xs[c][rg * 4];
                float4 gv = *(float4*)(s.gw[0] + c * 260 + cg * 4);
                unsigned long long g01 = ((unsigned long long*)&gv)[0];
                unsigned long long g23 = ((unsigned long long*)&gv)[1];
                unsigned long long x0 = pk2(xv.x), x1 = pk2(xv.y), x2 = pk2(xv.z), x3 = pk2(xv.w);
                fma2(a01[0], x0, g01); fma2(a23[0], x0, g23);
                fma2(a01[1], x1, g01); fma2(a23[1], x1, g23);
                fma2(a01[2], x2, g01); fma2(a23[2], x2, g23);
                fma2(a01[3], x3, g01); fma2(a23[3], x3, g23);
            }
            const int mb = mc * 256 + cg * 4;
            #pragma unroll
            for (int i = 0; i < 4; i++) {
                float4 o;
                ((unsigned long long*)&o)[0] = a01[i];
                ((unsigned long long*)&o)[1] = a23[i];
                *(float4*)&s.E[rg * 4 + i][mb] = o;
            }
            __syncthreads();
            if (mc < 3) {
                #pragma unroll
                for (int q = 0; q < 8; q++) {
                    int idx = q * 512 + t;
                    ((float4*)(s.gw[0] + (idx >> 6) * 260))[idx & 63] = pf[q];
                }
                __syncthreads();
            }
        }
    }

    // ---- softmax: 16 warps x 2 rows ----
    #pragma unroll
    for (int rr = 0; rr < 2; rr++) {
        const int r = w * 2 + rr;
        float pv[32];
        float mx = -1e30f;
        #pragma unroll
        for (int j = 0; j < 32; j++) { pv[j] = s.E[r][lane + 32 * j]; mx = fmaxf(mx, pv[j]); }
        #pragma unroll
        for (int o = 16; o; o >>= 1) mx = fmaxf(mx, __shfl_xor_sync(0xffffffffu, mx, o));
        float ss = 0.f;
        #pragma unroll
        for (int j = 0; j < 32; j++) { pv[j] = __expf((pv[j] - mx) * INV_SCALE); ss += pv[j]; }
        #pragma unroll
        for (int o = 16; o; o >>= 1) ss += __shfl_xor_sync(0xffffffffu, ss, o);
        const float rinv = 1.0f / ss;
        #pragma unroll
        for (int j = 0; j < 32; j++) s.E[r][lane + 32 * j] = pv[j] * rinv;
    }

    // initial WvT chunk 0 load (overlaps other warps' softmax; touches only gw)
    for (int i = t; i < 68 * 64; i += 512) {
        int cc = i >> 6, q = i & 63;
        ((float4*)(s.gw[0] + cc * 260))[q] = ((const float4*)(g_WvT[cc] + h * N_))[q];
    }
    __syncthreads();

    // ---- pass 2: V'(K=68) * probs, chunks of 256 d-cols, reg-prefetch ----
    {
        const int dg = w * 4 + (lane >> 3);   // d = dg*4
        const int ng = lane & 7;              // n = ng*4
        const size_t outbase = (size_t)b * 8192 + (size_t)h * N_;
        for (int dc = 0; dc < 4; dc++) {
            float4 pf[9];
            if (dc < 3) {
                #pragma unroll
                for (int q = 0; q < 9; q++) {
                    int idx = q * 512 + t;
                    if (idx < 68 * 64)
                        pf[q] = ((const float4*)(g_WvT[idx >> 6] + h * N_ + (dc + 1) * 256))[idx & 63];
                }
            }
            unsigned long long a01[4] = {}, a23[4] = {};
            #pragma unroll 4
            for (int cc = 0; cc < 68; cc++) {
                float4 xv = *(float4*)&s.nse[cc][ng * 4];
                float4 gv = *(float4*)(s.gw[0] + cc * 260 + dg * 4);
                unsigned long long g01 = ((unsigned long long*)&gv)[0];
                unsigned long long g23 = ((unsigned long long*)&gv)[1];
                unsigned long long x0 = pk2(xv.x), x1 = pk2(xv.y), x2 = pk2(xv.z), x3 = pk2(xv.w);
                fma2(a01[0], x0, g01); fma2(a23[0], x0, g23);
                fma2(a01[1], x1, g01); fma2(a23[1], x1, g23);
                fma2(a01[2], x2, g01); fma2(a23[2], x2, g23);
                fma2(a01[3], x3, g01); fma2(a23[3], x3, g23);
            }
            float vc[4][4];
            #pragma unroll
            for (int i = 0; i < 4; i++) {
                float4 Ev = *(float4*)&s.E[ng * 4 + i][dc * 256 + dg * 4];
                unsigned long long e01 = ((unsigned long long*)&Ev)[0];
                unsigned long long e23 = ((unsigned long long*)&Ev)[1];
                mul2(a01[i], a01[i], e01);
                mul2(a23[i], a23[i], e23);
                upk(a01[i], vc[i][0], vc[i][1]);
                upk(a23[i], vc[i][2], vc[i][3]);
            }
            #pragma unroll
            for (int k = 0; k < 4; k++) {
                size_t row = outbase + dc * 256 + dg * 4 + k;
                *(float4*)(out + row * N_ + n0 + ng * 4) =
                    make_float4(vc[0][k], vc[1][k], vc[2][k], vc[3][k]);
            }
            __syncthreads();
            if (dc < 3) {
                #pragma unroll
                for (int q = 0; q < 9; q++) {
                    int idx = q * 512 + t;
                    if (idx < 68 * 64)
                        ((float4*)(s.gw[0] + (idx >> 6) * 260))[idx & 63] = pf[q];
                }
                __syncthreads();
            }
        }
    }
}

// ============================================================
extern "C" void kernel_launch(void* const* d_in, const int* in_sizes, int n_in,
                              void* d_out, int out_size) {
    const float* coordinate = (const float*)d_in[0];
    const float* x          = (const float*)d_in[1];
    const float* neighbors  = (const float*)d_in[2];
    const float* Wq         = (const float*)d_in[3];
    const float* Wk         = (const float*)d_in[4];
    const float* Wv         = (const float*)d_in[5];
    const float* Wlq        = (const float*)d_in[6];
    const float* blq        = (const float*)d_in[7];
    const float* Wlv        = (const float*)d_in[8];
    const float* blv        = (const float*)d_in[9];
    float* out = (float*)d_out;

    static bool attr_set = false;
    if (!attr_set) {
        cudaFuncSetAttribute(k_main, cudaFuncAttributeMaxDynamicSharedMemorySize, 220 * 1024);
        attr_set = true;
    }

    k_prep1<<<dim3(H_, 16), 256>>>(Wq, Wk, Wlq, blq);
    k_prep2<<<dim3(H_, 16), 256>>>();
    k_wvT<<<256, 256>>>(Wv, Wlv, blv);
    k_buildG<<<dim3(B_ * H_, 16), 256>>>(neighbors, coordinate);
    k_main<<<dim3(B_ * H_, 32), 512, sizeof(SM3)>>>(x, neighbors, coordinate, out);
}